// round 14
// baseline (speedup 1.0000x reference)
#include <cuda_runtime.h>
#include <cstdint>

// Problem constants
#define BB 4
#define SS 4096
#define DD 2048
#define LL 3
#define TRIPLE (3 * DD)
#define MTOT (BB * SS)          // 16384

// GEMM tiling: CTA 128x128, 4 warps (2x2), warp tile 64x64, BK=32,
// 3-stage cp.async, 2 CTAs/SM, single barrier per k-tile.
// B smem: [16][264] pair-interleaved (one LDS.64 per B frag).
// A smem (ATRANS=1): [32][136] k-major, m-pairs interleaved (LDS.64 frags).
// A smem (ATRANS=0): [128][36] natural (round-12 proven).
#define BM 128
#define BN 128
#define BK 32
#define NSTAGE 3
#define AST_N 36
#define AST_T 136
#define A_SM 4608               // max(128*36, 32*136) floats
#define BST 264
#define B_SM (16 * BST)         // 4224 floats
#define STG_FLT (A_SM + B_SM)   // 8832 floats
#define SMEM_BYTES (NSTAGE * STG_FLT * 4)   // 105984 B

// Scratch (__device__ globals: allocation-free rule)
__device__ float g_Bx[(size_t)MTOT * DD];        // B_gate*x_proj (GEMM1 epilogue)
__device__ float g_Cg[(size_t)MTOT * DD];        // C_gate
__device__ float g_y[(size_t)MTOT * DD];         // GEMM2 A (tf32, natural [M][K])
__device__ float g_xt[(size_t)DD * MTOT];        // x (tf32, [K][M] m-pair-interleaved)
__device__ float g_Win[(size_t)DD * TRIPLE];     // W_in  remapped+interleaved [K/2][2N]
__device__ float g_Wout[(size_t)DD * DD];        // W_out interleaved [K/2][2N]

__device__ __forceinline__ float f2tf32(float x) {
    float r;
    asm("cvt.rna.tf32.f32 %0, %1;" : "=f"(r) : "f"(x));
    return r;
}

__device__ __forceinline__ uint32_t smem_u32(const void* p) {
    uint32_t a;
    asm("{ .reg .u64 t; cvta.to.shared.u64 t, %1; cvt.u32.u64 %0, t; }" : "=r"(a) : "l"(p));
    return a;
}

#define CP_ASYNC16(dst, src) \
    asm volatile("cp.async.cg.shared.global [%0], [%1], 16;" :: "r"(dst), "l"(src))
#define CP_COMMIT() asm volatile("cp.async.commit_group;" ::: "memory")
#define CP_WAIT1()  asm volatile("cp.async.wait_group 1;" ::: "memory")

__device__ __forceinline__ void mma_tf32(float c[4], const uint32_t a[4], const uint32_t b[2]) {
    asm volatile(
        "mma.sync.aligned.m16n8k8.row.col.f32.tf32.tf32.f32 "
        "{%0,%1,%2,%3}, {%4,%5,%6,%7}, {%8,%9}, {%0,%1,%2,%3};"
        : "+f"(c[0]), "+f"(c[1]), "+f"(c[2]), "+f"(c[3])
        : "r"(a[0]), "r"(a[1]), "r"(a[2]), "r"(a[3]), "r"(b[0]), "r"(b[1]));
}

// ---------------------------------------------------------------------------
// TF32 mma.sync GEMM. B pre-interleaved [K/2][2N].
// ATRANS=0: A row-major [M][K]. ATRANS=1: A k-major [K][MTOT], m-pairs
//   (16g+j, 16g+j+8) adjacent within each 128-row panel.
// MODE 0: plain C[M][N] write. MODE 1: gated GEMM1 epilogue (Bx / C_gate).
// ---------------------------------------------------------------------------
template <int MODE, int ATRANS>
__global__ __launch_bounds__(128, 2)
void tf32_gemm(const float* __restrict__ A, const float* __restrict__ B,
               float* __restrict__ C, float* __restrict__ CBx,
               float* __restrict__ CCg, int N, int K) {
    extern __shared__ float sm[];
    const uint32_t smb = smem_u32(sm);

    const int tid    = threadIdx.x;
    const int wid    = tid >> 5;
    const int lane   = tid & 31;
    const int warp_m = wid >> 1;      // 0..1
    const int warp_n = wid & 1;       // 0..1
    const int lr     = lane >> 2;     // 0..7
    const int lc     = lane & 3;      // 0..3

    const int brow = blockIdx.y * BM;
    const int bcol = blockIdx.x * BN;

    const float* Ap = ATRANS ? A + brow : A + (size_t)brow * K;
    const float* Bp = B + 2 * (size_t)bcol;
    const size_t brs = 2 * (size_t)N;   // interleaved B row stride (floats)

    // cp.async coords
    const int arow0 = tid >> 3;             // natural-A: +i*16
    const int akc   = (tid & 7) * 4;
    const int tkr   = tid >> 5;             // trans-A: k row +i*4
    const int tcc   = (tid & 31) * 4;       // trans-A: m offset
    const int brw   = tid >> 3;
    const int bcc   = (tid & 7) * 4;

    auto issue = [&](int kt, int buf) {
        uint32_t as = smb + (uint32_t)buf * STG_FLT * 4;
        uint32_t bs = as + A_SM * 4;
        if (ATRANS) {
            const float* asrc = Ap + (size_t)(kt * BK) * MTOT;
            #pragma unroll
            for (int i = 0; i < 8; i++) {
                int k = tkr + i * 4;
                CP_ASYNC16(as + (uint32_t)(k * AST_T + tcc) * 4,
                           asrc + (size_t)k * MTOT + tcc);
            }
        } else {
            #pragma unroll
            for (int i = 0; i < 8; i++) {
                int m = arow0 + i * 16;
                CP_ASYNC16(as + (uint32_t)(m * AST_N + akc) * 4,
                           Ap + (size_t)m * K + kt * BK + akc);
            }
        }
        const float* bsrc = Bp + (size_t)(16 * kt + brw) * brs;
        #pragma unroll
        for (int i = 0; i < 8; i++) {
            int c = bcc + i * 32;
            CP_ASYNC16(bs + (uint32_t)(brw * BST + c) * 4, bsrc + c);
        }
    };

    float acc[4][8][4];
    #pragma unroll
    for (int mi = 0; mi < 4; mi++)
        #pragma unroll
        for (int ni = 0; ni < 8; ni++)
            #pragma unroll
            for (int q = 0; q < 4; q++)
                acc[mi][ni][q] = 0.0f;

    const int NK = K / BK;

    issue(0, 0); CP_COMMIT();
    issue(1, 1); CP_COMMIT();

    int buf = 0;
    for (int kt = 0; kt < NK; kt++) {
        CP_WAIT1();
        __syncthreads();

        if (kt + 2 < NK) {
            int nbuf = buf + 2; if (nbuf >= NSTAGE) nbuf -= NSTAGE;
            issue(kt + 2, nbuf);
        }
        CP_COMMIT();

        const float* As = sm + (size_t)buf * STG_FLT;
        const float* Bs = As + A_SM;

        #pragma unroll
        for (int ks = 0; ks < 4; ks++) {
            const int k0 = ks * 8;
            uint32_t a[4][4];
            if (ATRANS) {
                #pragma unroll
                for (int mi = 0; mi < 4; mi++) {
                    const float* p = As + (k0 + lc) * AST_T
                                   + 16 * (warp_m * 4 + mi) + 2 * lr;
                    float2 v0 = *(const float2*)p;              // rows r, r+8 @ k0+lc
                    float2 v1 = *(const float2*)(p + 4 * AST_T); // @ k0+lc+4
                    a[mi][0] = __float_as_uint(v0.x);
                    a[mi][1] = __float_as_uint(v0.y);
                    a[mi][2] = __float_as_uint(v1.x);
                    a[mi][3] = __float_as_uint(v1.y);
                }
            } else {
                #pragma unroll
                for (int mi = 0; mi < 4; mi++) {
                    const int base = (warp_m * 64 + mi * 16 + lr) * AST_N + k0 + lc;
                    a[mi][0] = __float_as_uint(As[base]);
                    a[mi][1] = __float_as_uint(As[base + 8 * AST_N]);
                    a[mi][2] = __float_as_uint(As[base + 4]);
                    a[mi][3] = __float_as_uint(As[base + 8 * AST_N + 4]);
                }
            }
            uint32_t b[8][2];
            #pragma unroll
            for (int ni = 0; ni < 8; ni++) {
                const int n = warp_n * 64 + ni * 8 + lr;
                float2 v = *(const float2*)(Bs + (ks * 4 + lc) * BST + 2 * n);
                b[ni][0] = __float_as_uint(v.x);
                b[ni][1] = __float_as_uint(v.y);
            }
            #pragma unroll
            for (int mi = 0; mi < 4; mi++)
                #pragma unroll
                for (int ni = 0; ni < 8; ni++)
                    mma_tf32(acc[mi][ni], a[mi], b[ni]);
        }

        if (++buf == NSTAGE) buf = 0;
    }

    // Epilogue
    if (MODE == 0) {
        #pragma unroll
        for (int mi = 0; mi < 4; mi++) {
            #pragma unroll
            for (int ni = 0; ni < 8; ni++) {
                const int r0 = brow + warp_m * 64 + mi * 16 + lr;
                const int c0 = bcol + warp_n * 64 + ni * 8 + lc * 2;
                *(float2*)(C + (size_t)r0 * N + c0)       = make_float2(acc[mi][ni][0], acc[mi][ni][1]);
                *(float2*)(C + (size_t)(r0 + 8) * N + c0) = make_float2(acc[mi][ni][2], acc[mi][ni][3]);
            }
        }
    } else if (bcol < 2 * DD) {
        // gated pairs: thread cols (c0, c0+1) = (B_gate_d, x_proj_d)
        #pragma unroll
        for (int mi = 0; mi < 4; mi++) {
            #pragma unroll
            for (int ni = 0; ni < 8; ni++) {
                const int r0 = brow + warp_m * 64 + mi * 16 + lr;
                const int d  = (bcol + warp_n * 64 + ni * 8 + lc * 2) >> 1;
                CBx[(size_t)r0 * DD + d]       = acc[mi][ni][0] * acc[mi][ni][1];
                CBx[(size_t)(r0 + 8) * DD + d] = acc[mi][ni][2] * acc[mi][ni][3];
            }
        }
    } else {
        #pragma unroll
        for (int mi = 0; mi < 4; mi++) {
            #pragma unroll
            for (int ni = 0; ni < 8; ni++) {
                const int r0 = brow + warp_m * 64 + mi * 16 + lr;
                const int c0 = bcol - 2 * DD + warp_n * 64 + ni * 8 + lc * 2;
                *(float2*)(CCg + (size_t)r0 * DD + c0)       = make_float2(acc[mi][ni][0], acc[mi][ni][1]);
                *(float2*)(CCg + (size_t)(r0 + 8) * DD + c0) = make_float2(acc[mi][ni][2], acc[mi][ni][3]);
            }
        }
    }
}

// ---------------------------------------------------------------------------
// x [M][K] -> xt [K][M], tf32-rounded, m-pair-interleaved per 128-panel:
//   pos(m) = panel*128 + 16*(r/16) + 2*(r%8) + ((r%16)/8),  r = m%128
// ---------------------------------------------------------------------------
__global__ void xtrans_kernel(const float* __restrict__ in, float* __restrict__ out) {
    __shared__ float s[32][33];
    const int mb = blockIdx.y * 32, kb = blockIdx.x * 32;
    const int tx = threadIdx.x, ty = threadIdx.y;

    #pragma unroll
    for (int j = 0; j < 4; j++)
        s[ty + 8 * j][tx] = f2tf32(in[(size_t)(mb + ty + 8 * j) * DD + kb + tx]);
    __syncthreads();

    const int m = mb + tx;
    const int r = m & 127;
    const int posm = (m - r) + 16 * (r >> 4) + 2 * (r & 7) + ((r >> 3) & 1);
    #pragma unroll
    for (int j = 0; j < 4; j++)
        out[(size_t)(kb + ty + 8 * j) * MTOT + posm] = s[tx][ty + 8 * j];
}

// ---------------------------------------------------------------------------
// W [K][N] -> pair-interleaved [K/2][2N'], optional source-column remap:
//   remap(n) = n<4096 ? (n odd ? 2D+n/2 : n/2) : D + (n-4096)
// ---------------------------------------------------------------------------
template <int REMAP>
__global__ void wtrans_kernel(const float* __restrict__ in, float* __restrict__ out,
                              int N) {
    __shared__ float s[8][257];
    const int kb = blockIdx.y;
    const int n0 = blockIdx.x * 256;
    const int tid = threadIdx.x;

    int n = n0 + tid;
    int src;
    if (REMAP) {
        src = (n < 2 * DD) ? ((n & 1) ? 2 * DD + (n >> 1) : (n >> 1))
                           : DD + (n - 2 * DD);
    } else {
        src = n;
    }
    #pragma unroll
    for (int j = 0; j < 8; j++)
        s[j][tid] = f2tf32(in[(size_t)(kb * 8 + j) * N + src]);
    __syncthreads();

    const int p  = tid >> 6;
    const int j0 = tid & 63;
    #pragma unroll
    for (int h = 0; h < 2; h++) {
        int j = j0 + h * 64;
        float4 v = make_float4(s[p][2 * j], s[p + 4][2 * j],
                               s[p][2 * j + 1], s[p + 4][2 * j + 1]);
        *(float4*)(out + (size_t)(kb * 4 + p) * (2 * N) + 2 * n0 + 4 * j) = v;
    }
}

// ---------------------------------------------------------------------------
// Conv + gate from precomputed Bx and C_gate:
// y = tf32( Cg[s] * (w2*Bx[s] + w1*Bx[s-1] + w0*Bx[s-2]) )   (natural layout)
// ---------------------------------------------------------------------------
__global__ void conv_gate_kernel(const float* __restrict__ conv_w,
                                 float* __restrict__ y) {
    const size_t total = (size_t)MTOT * (DD / 4);
    size_t idx = (size_t)blockIdx.x * blockDim.x + threadIdx.x;
    if (idx >= total) return;

    const int    d4 = (int)(idx % (DD / 4));
    const size_t bs = idx / (DD / 4);
    const int    s  = (int)(bs % SS);
    const int    d  = d4 * 4;

    float4 bx0 = *(const float4*)(g_Bx + bs * DD + d);
    float4 bx1 = (s >= 1) ? *(const float4*)(g_Bx + (bs - 1) * DD + d)
                          : make_float4(0.f, 0.f, 0.f, 0.f);
    float4 bx2 = (s >= 2) ? *(const float4*)(g_Bx + (bs - 2) * DD + d)
                          : make_float4(0.f, 0.f, 0.f, 0.f);
    float4 cg  = *(const float4*)(g_Cg + bs * DD + d);

    float o[4];
    const float* b0 = &bx0.x;
    const float* b1 = &bx1.x;
    const float* b2 = &bx2.x;
    const float* cgp = &cg.x;
    #pragma unroll
    for (int j = 0; j < 4; j++) {
        const int dj = d + j;
        const float w0 = conv_w[dj * LL + 0];
        const float w1 = conv_w[dj * LL + 1];
        const float w2 = conv_w[dj * LL + 2];
        float conv = w2 * b0[j] + w1 * b1[j] + w0 * b2[j];
        o[j] = f2tf32(cgp[j] * conv);
    }
    *(float4*)(y + bs * DD + d) = make_float4(o[0], o[1], o[2], o[3]);
}

// ---------------------------------------------------------------------------
extern "C" void kernel_launch(void* const* d_in, const int* in_sizes, int n_in,
                              void* d_out, int out_size) {
    const float* x      = (const float*)d_in[0];
    const float* W_in   = (const float*)d_in[1];
    const float* conv_w = (const float*)d_in[2];
    const float* W_out  = (const float*)d_in[3];
    float*       out    = (float*)d_out;

    float *Bx, *Cg, *y, *xt, *Win, *Wout;
    cudaGetSymbolAddress((void**)&Bx,   g_Bx);
    cudaGetSymbolAddress((void**)&Cg,   g_Cg);
    cudaGetSymbolAddress((void**)&y,    g_y);
    cudaGetSymbolAddress((void**)&xt,   g_xt);
    cudaGetSymbolAddress((void**)&Win,  g_Win);
    cudaGetSymbolAddress((void**)&Wout, g_Wout);

    cudaFuncSetAttribute((const void*)tf32_gemm<1, 1>,
                         cudaFuncAttributeMaxDynamicSharedMemorySize, SMEM_BYTES);
    cudaFuncSetAttribute((const void*)tf32_gemm<0, 0>,
                         cudaFuncAttributeMaxDynamicSharedMemorySize, SMEM_BYTES);

    // Pre-passes: x transpose+round, weight transforms
    xtrans_kernel<<<dim3(DD / 32, MTOT / 32), dim3(32, 8)>>>(x, xt);
    wtrans_kernel<1><<<dim3(TRIPLE / 256, DD / 8), 256>>>(W_in, Win, TRIPLE);
    wtrans_kernel<0><<<dim3(DD / 256, DD / 8), 256>>>(W_out, Wout, DD);

    // GEMM1 (gated, A-transposed): writes Bx and C_gate directly
    tf32_gemm<1, 1><<<dim3(TRIPLE / BN, MTOT / BM), 128, SMEM_BYTES>>>(
        xt, Win, nullptr, Bx, Cg, TRIPLE, DD);

    // Conv + gate -> y (tf32-rounded)
    {
        size_t total = (size_t)MTOT * (DD / 4);
        conv_gate_kernel<<<(unsigned)((total + 255) / 256), 256>>>(conv_w, y);
    }

    // GEMM2: out = y @ W_out (natural A path)
    tf32_gemm<0, 0><<<dim3(DD / BN, MTOT / BM), 128, SMEM_BYTES>>>(
        y, Wout, out, nullptr, nullptr, DD, DD);
}

// round 15
// speedup vs baseline: 1.4603x; 1.4603x over previous
#include <cuda_runtime.h>
#include <cstdint>

// Problem constants
#define BB 4
#define SS 4096
#define DD 2048
#define LL 3
#define TRIPLE (3 * DD)
#define MTOT (BB * SS)          // 16384

// GEMM tiling: CTA 128x128, 4 warps (2x2), warp tile 64x64, BK=32,
// 3-stage cp.async, 2 CTAs/SM, single barrier per k-tile.
// A smem: [128][36] natural. B smem: [16][264] pair-interleaved (LDS.64 frags).
#define BM 128
#define BN 128
#define BK 32
#define NSTAGE 3
#define AST 36
#define BST 264
#define A_SM (BM * AST)         // 4608 floats
#define B_SM (16 * BST)         // 4224 floats
#define STG_FLT (A_SM + B_SM)   // 8832 floats
#define SMEM_BYTES (NSTAGE * STG_FLT * 4)   // 105984 B

// Scratch (__device__ globals: allocation-free rule)
__device__ float g_Bx[(size_t)MTOT * DD];        // B_gate*x_proj (GEMM1 epilogue)
__device__ float g_Cg[(size_t)MTOT * DD];        // C_gate
__device__ float g_y[(size_t)MTOT * DD];         // GEMM2 A (tf32-rounded)
__device__ float g_xc[(size_t)MTOT * DD];        // x tf32-rounded
__device__ float g_Win[(size_t)DD * TRIPLE];     // W_in  remapped+interleaved [K/2][2N]
__device__ float g_Wout[(size_t)DD * DD];        // W_out interleaved [K/2][2N]

__device__ __forceinline__ float f2tf32(float x) {
    float r;
    asm("cvt.rna.tf32.f32 %0, %1;" : "=f"(r) : "f"(x));
    return r;
}

__device__ __forceinline__ uint32_t smem_u32(const void* p) {
    uint32_t a;
    asm("{ .reg .u64 t; cvta.to.shared.u64 t, %1; cvt.u32.u64 %0, t; }" : "=r"(a) : "l"(p));
    return a;
}

#define CP_ASYNC16(dst, src) \
    asm volatile("cp.async.cg.shared.global [%0], [%1], 16;" :: "r"(dst), "l"(src))
#define CP_COMMIT() asm volatile("cp.async.commit_group;" ::: "memory")
#define CP_WAIT1()  asm volatile("cp.async.wait_group 1;" ::: "memory")

__device__ __forceinline__ void mma_tf32(float c[4], const uint32_t a[4], const uint32_t b[2]) {
    asm volatile(
        "mma.sync.aligned.m16n8k8.row.col.f32.tf32.tf32.f32 "
        "{%0,%1,%2,%3}, {%4,%5,%6,%7}, {%8,%9}, {%0,%1,%2,%3};"
        : "+f"(c[0]), "+f"(c[1]), "+f"(c[2]), "+f"(c[3])
        : "r"(a[0]), "r"(a[1]), "r"(a[2]), "r"(a[3]), "r"(b[0]), "r"(b[1]));
}

// ---------------------------------------------------------------------------
// TF32 mma.sync GEMM. A row-major (tf32-pre-rounded), B pre-interleaved
// [K/2][2N]. MODE 0: plain C[M][N] write.
// MODE 1 (GEMM1 gated): cols 2d/2d+1 (n<4096) hold (B_gate_d, x_proj_d),
//   cols 4096+d hold C_gate_d. Epilogue writes Bx = accEven*accOdd and C_gate.
// ---------------------------------------------------------------------------
template <int MODE>
__global__ __launch_bounds__(128, 2)
void tf32_gemm(const float* __restrict__ A, const float* __restrict__ B,
               float* __restrict__ C, float* __restrict__ CBx,
               float* __restrict__ CCg, int N, int K) {
    extern __shared__ float sm[];
    const uint32_t smb = smem_u32(sm);

    const int tid    = threadIdx.x;
    const int wid    = tid >> 5;
    const int lane   = tid & 31;
    const int warp_m = wid >> 1;      // 0..1
    const int warp_n = wid & 1;       // 0..1
    const int lr     = lane >> 2;     // 0..7
    const int lc     = lane & 3;      // 0..3

    const int brow = blockIdx.y * BM;
    const int bcol = blockIdx.x * BN;

    const float* Ap = A + (size_t)brow * K;
    const float* Bp = B + 2 * (size_t)bcol;
    const size_t brs = 2 * (size_t)N;   // interleaved B row stride (floats)

    const int arow0 = tid >> 3;
    const int akc   = (tid & 7) * 4;
    const int brw   = tid >> 3;
    const int bcc   = (tid & 7) * 4;

    auto issue = [&](int kt, int buf) {
        uint32_t as = smb + (uint32_t)buf * STG_FLT * 4;
        uint32_t bs = as + A_SM * 4;
        #pragma unroll
        for (int i = 0; i < 8; i++) {
            int m = arow0 + i * 16;
            CP_ASYNC16(as + (uint32_t)(m * AST + akc) * 4,
                       Ap + (size_t)m * K + kt * BK + akc);
        }
        const float* bsrc = Bp + (size_t)(16 * kt + brw) * brs;
        #pragma unroll
        for (int i = 0; i < 8; i++) {
            int c = bcc + i * 32;
            CP_ASYNC16(bs + (uint32_t)(brw * BST + c) * 4, bsrc + c);
        }
    };

    float acc[4][8][4];
    #pragma unroll
    for (int mi = 0; mi < 4; mi++)
        #pragma unroll
        for (int ni = 0; ni < 8; ni++)
            #pragma unroll
            for (int q = 0; q < 4; q++)
                acc[mi][ni][q] = 0.0f;

    const int NK = K / BK;

    issue(0, 0); CP_COMMIT();
    issue(1, 1); CP_COMMIT();

    int buf = 0;
    for (int kt = 0; kt < NK; kt++) {
        CP_WAIT1();
        __syncthreads();

        if (kt + 2 < NK) {
            int nbuf = buf + 2; if (nbuf >= NSTAGE) nbuf -= NSTAGE;
            issue(kt + 2, nbuf);
        }
        CP_COMMIT();

        const float* As = sm + (size_t)buf * STG_FLT;
        const float* Bs = As + A_SM;

        #pragma unroll
        for (int ks = 0; ks < 4; ks++) {
            const int k0 = ks * 8;
            uint32_t a[4][4];
            #pragma unroll
            for (int mi = 0; mi < 4; mi++) {
                const int base = (warp_m * 64 + mi * 16 + lr) * AST + k0 + lc;
                a[mi][0] = __float_as_uint(As[base]);
                a[mi][1] = __float_as_uint(As[base + 8 * AST]);
                a[mi][2] = __float_as_uint(As[base + 4]);
                a[mi][3] = __float_as_uint(As[base + 8 * AST + 4]);
            }
            uint32_t b[8][2];
            #pragma unroll
            for (int ni = 0; ni < 8; ni++) {
                const int n = warp_n * 64 + ni * 8 + lr;
                float2 v = *(const float2*)(Bs + (ks * 4 + lc) * BST + 2 * n);
                b[ni][0] = __float_as_uint(v.x);
                b[ni][1] = __float_as_uint(v.y);
            }
            #pragma unroll
            for (int mi = 0; mi < 4; mi++)
                #pragma unroll
                for (int ni = 0; ni < 8; ni++)
                    mma_tf32(acc[mi][ni], a[mi], b[ni]);
        }

        if (++buf == NSTAGE) buf = 0;
    }

    // Epilogue
    if (MODE == 0) {
        #pragma unroll
        for (int mi = 0; mi < 4; mi++) {
            #pragma unroll
            for (int ni = 0; ni < 8; ni++) {
                const int r0 = brow + warp_m * 64 + mi * 16 + lr;
                const int c0 = bcol + warp_n * 64 + ni * 8 + lc * 2;
                *(float2*)(C + (size_t)r0 * N + c0)       = make_float2(acc[mi][ni][0], acc[mi][ni][1]);
                *(float2*)(C + (size_t)(r0 + 8) * N + c0) = make_float2(acc[mi][ni][2], acc[mi][ni][3]);
            }
        }
    } else if (bcol < 2 * DD) {
        // gated pairs: thread cols (c0, c0+1) = (B_gate_d, x_proj_d)
        #pragma unroll
        for (int mi = 0; mi < 4; mi++) {
            #pragma unroll
            for (int ni = 0; ni < 8; ni++) {
                const int r0 = brow + warp_m * 64 + mi * 16 + lr;
                const int d  = (bcol + warp_n * 64 + ni * 8 + lc * 2) >> 1;
                CBx[(size_t)r0 * DD + d]       = acc[mi][ni][0] * acc[mi][ni][1];
                CBx[(size_t)(r0 + 8) * DD + d] = acc[mi][ni][2] * acc[mi][ni][3];
            }
        }
    } else {
        #pragma unroll
        for (int mi = 0; mi < 4; mi++) {
            #pragma unroll
            for (int ni = 0; ni < 8; ni++) {
                const int r0 = brow + warp_m * 64 + mi * 16 + lr;
                const int c0 = bcol - 2 * DD + warp_n * 64 + ni * 8 + lc * 2;
                *(float2*)(CCg + (size_t)r0 * DD + c0)       = make_float2(acc[mi][ni][0], acc[mi][ni][1]);
                *(float2*)(CCg + (size_t)(r0 + 8) * DD + c0) = make_float2(acc[mi][ni][2], acc[mi][ni][3]);
            }
        }
    }
}

// ---------------------------------------------------------------------------
// Elementwise tf32 rounding (float4 vectorized)
// ---------------------------------------------------------------------------
__global__ void cvt_tf32_kernel(const float* __restrict__ in, float* __restrict__ out,
                                size_t n4) {
    size_t i = (size_t)blockIdx.x * blockDim.x + threadIdx.x;
    if (i >= n4) return;
    float4 v = ((const float4*)in)[i];
    v.x = f2tf32(v.x); v.y = f2tf32(v.y); v.z = f2tf32(v.z); v.w = f2tf32(v.w);
    ((float4*)out)[i] = v;
}

// ---------------------------------------------------------------------------
// W [K][N] -> pair-interleaved [K/2][2N'], optional source-column remap:
//   remap(n) = n<4096 ? (n odd ? 2D+n/2 : n/2) : D + (n-4096)
// out[kb*4+p][2n+h] = tf32(W[kb*8+p+4h][remap(n)]).
// ---------------------------------------------------------------------------
template <int REMAP>
__global__ void wtrans_kernel(const float* __restrict__ in, float* __restrict__ out,
                              int N) {
    __shared__ float s[8][257];
    const int kb = blockIdx.y;
    const int n0 = blockIdx.x * 256;
    const int tid = threadIdx.x;

    int n = n0 + tid;
    int src;
    if (REMAP) {
        src = (n < 2 * DD) ? ((n & 1) ? 2 * DD + (n >> 1) : (n >> 1))
                           : DD + (n - 2 * DD);
    } else {
        src = n;
    }
    #pragma unroll
    for (int j = 0; j < 8; j++)
        s[j][tid] = f2tf32(in[(size_t)(kb * 8 + j) * N + src]);
    __syncthreads();

    const int p  = tid >> 6;
    const int j0 = tid & 63;
    #pragma unroll
    for (int h = 0; h < 2; h++) {
        int j = j0 + h * 64;
        float4 v = make_float4(s[p][2 * j], s[p + 4][2 * j],
                               s[p][2 * j + 1], s[p + 4][2 * j + 1]);
        *(float4*)(out + (size_t)(kb * 4 + p) * (2 * N) + 2 * n0 + 4 * j) = v;
    }
}

// ---------------------------------------------------------------------------
// Conv + gate from precomputed Bx and C_gate, with conv_w staged in smem.
// One block (256 thr) per (b,s) row; each thread handles 8 d's.
// y = tf32( Cg[s] * (w2*Bx[s] + w1*Bx[s-1] + w0*Bx[s-2]) )
// ---------------------------------------------------------------------------
__global__ __launch_bounds__(256)
void conv_gate_kernel(const float* __restrict__ conv_w,
                      float* __restrict__ y) {
    __shared__ float wsm[DD * LL];          // 24 KB
    const int m = blockIdx.x;               // 0..MTOT-1
    const int s = m & (SS - 1);
    const int t = threadIdx.x;

    // coalesced float4 staging of conv_w (6144 floats, 256 thr -> 6 f4 each)
    #pragma unroll
    for (int i = 0; i < 6; i++)
        ((float4*)wsm)[t + i * 256] = ((const float4*)conv_w)[t + i * 256];
    __syncthreads();

    const float* bx0p = g_Bx + (size_t)m * DD;
    const float* cgp  = g_Cg + (size_t)m * DD;
    float* yp = y + (size_t)m * DD;

    #pragma unroll
    for (int g = 0; g < 2; g++) {
        const int d = t * 4 + g * 1024;
        float4 bx0 = *(const float4*)(bx0p + d);
        float4 bx1 = (s >= 1) ? *(const float4*)(bx0p - DD + d)
                              : make_float4(0.f, 0.f, 0.f, 0.f);
        float4 bx2 = (s >= 2) ? *(const float4*)(bx0p - 2 * DD + d)
                              : make_float4(0.f, 0.f, 0.f, 0.f);
        float4 cg = *(const float4*)(cgp + d);

        const float* b0 = &bx0.x;
        const float* b1 = &bx1.x;
        const float* b2 = &bx2.x;
        const float* cgv = &cg.x;
        float o[4];
        #pragma unroll
        for (int j = 0; j < 4; j++) {
            const float* w = wsm + (d + j) * LL;
            float conv = w[2] * b0[j] + w[1] * b1[j] + w[0] * b2[j];
            o[j] = f2tf32(cgv[j] * conv);
        }
        *(float4*)(yp + d) = make_float4(o[0], o[1], o[2], o[3]);
    }
}

// ---------------------------------------------------------------------------
extern "C" void kernel_launch(void* const* d_in, const int* in_sizes, int n_in,
                              void* d_out, int out_size) {
    const float* x      = (const float*)d_in[0];
    const float* W_in   = (const float*)d_in[1];
    const float* conv_w = (const float*)d_in[2];
    const float* W_out  = (const float*)d_in[3];
    float*       out    = (float*)d_out;

    float *Bx, *Cg, *y, *xc, *Win, *Wout;
    cudaGetSymbolAddress((void**)&Bx,   g_Bx);
    cudaGetSymbolAddress((void**)&Cg,   g_Cg);
    cudaGetSymbolAddress((void**)&y,    g_y);
    cudaGetSymbolAddress((void**)&xc,   g_xc);
    cudaGetSymbolAddress((void**)&Win,  g_Win);
    cudaGetSymbolAddress((void**)&Wout, g_Wout);

    cudaFuncSetAttribute((const void*)tf32_gemm<1>,
                         cudaFuncAttributeMaxDynamicSharedMemorySize, SMEM_BYTES);
    cudaFuncSetAttribute((const void*)tf32_gemm<0>,
                         cudaFuncAttributeMaxDynamicSharedMemorySize, SMEM_BYTES);

    // Pre-passes: tf32 rounding (x) + weight transforms
    {
        size_t n4 = (size_t)MTOT * DD / 4;
        cvt_tf32_kernel<<<(unsigned)((n4 + 255) / 256), 256>>>(x, xc, n4);
        wtrans_kernel<1><<<dim3(TRIPLE / 256, DD / 8), 256>>>(W_in, Win, TRIPLE);
        wtrans_kernel<0><<<dim3(DD / 256, DD / 8), 256>>>(W_out, Wout, DD);
    }

    // GEMM1 (gated): writes Bx = B_gate*x_proj and C_gate directly
    tf32_gemm<1><<<dim3(TRIPLE / BN, MTOT / BM), 128, SMEM_BYTES>>>(
        xc, Win, nullptr, Bx, Cg, TRIPLE, DD);

    // Conv + gate -> y (tf32-rounded)
    conv_gate_kernel<<<MTOT, 256>>>(conv_w, y);

    // GEMM2: out = y @ W_out
    tf32_gemm<0><<<dim3(DD / BN, MTOT / BM), 128, SMEM_BYTES>>>(
        y, Wout, out, nullptr, nullptr, DD, DD);
}

// round 16
// speedup vs baseline: 1.4680x; 1.0053x over previous
#include <cuda_runtime.h>
#include <cuda_fp16.h>
#include <cstdint>

// Problem constants
#define BB 4
#define SS 4096
#define DD 2048
#define LL 3
#define TRIPLE (3 * DD)
#define MTOT (BB * SS)          // 16384

// GEMM tiling: CTA 128x128, 4 warps (2x2), warp tile 64x64, BK=32,
// 3-stage cp.async, 2 CTAs/SM, single barrier per k-tile.
// A smem: [128][36] natural. B smem: [16][264] pair-interleaved (LDS.64 frags).
#define BM 128
#define BN 128
#define BK 32
#define NSTAGE 3
#define AST 36
#define BST 264
#define A_SM (BM * AST)         // 4608 floats
#define B_SM (16 * BST)         // 4224 floats
#define STG_FLT (A_SM + B_SM)   // 8832 floats
#define SMEM_BYTES (NSTAGE * STG_FLT * 4)   // 105984 B

// Scratch (__device__ globals: allocation-free rule)
__device__ __half g_BxH[(size_t)MTOT * DD];      // B_gate*x_proj (fp16, GEMM1 epilogue)
__device__ __half g_CgH[(size_t)MTOT * DD];      // C_gate (fp16)
__device__ float  g_y[(size_t)MTOT * DD];        // GEMM2 A (tf32-rounded)
__device__ float  g_xc[(size_t)MTOT * DD];       // x tf32-rounded
__device__ float  g_Win[(size_t)DD * TRIPLE];    // W_in  remapped+interleaved [K/2][2N]
__device__ float  g_Wout[(size_t)DD * DD];       // W_out interleaved [K/2][2N]

__device__ __forceinline__ float f2tf32(float x) {
    float r;
    asm("cvt.rna.tf32.f32 %0, %1;" : "=f"(r) : "f"(x));
    return r;
}

__device__ __forceinline__ uint32_t smem_u32(const void* p) {
    uint32_t a;
    asm("{ .reg .u64 t; cvta.to.shared.u64 t, %1; cvt.u32.u64 %0, t; }" : "=r"(a) : "l"(p));
    return a;
}

#define CP_ASYNC16(dst, src) \
    asm volatile("cp.async.cg.shared.global [%0], [%1], 16;" :: "r"(dst), "l"(src))
#define CP_COMMIT() asm volatile("cp.async.commit_group;" ::: "memory")
#define CP_WAIT1()  asm volatile("cp.async.wait_group 1;" ::: "memory")

__device__ __forceinline__ void mma_tf32(float c[4], const uint32_t a[4], const uint32_t b[2]) {
    asm volatile(
        "mma.sync.aligned.m16n8k8.row.col.f32.tf32.tf32.f32 "
        "{%0,%1,%2,%3}, {%4,%5,%6,%7}, {%8,%9}, {%0,%1,%2,%3};"
        : "+f"(c[0]), "+f"(c[1]), "+f"(c[2]), "+f"(c[3])
        : "r"(a[0]), "r"(a[1]), "r"(a[2]), "r"(a[3]), "r"(b[0]), "r"(b[1]));
}

// ---------------------------------------------------------------------------
// TF32 mma.sync GEMM. A row-major (tf32-pre-rounded), B pre-interleaved
// [K/2][2N]. MODE 0: plain C[M][N] write.
// MODE 1 (GEMM1 gated): cols 2d/2d+1 (n<4096) hold (B_gate_d, x_proj_d),
//   cols 4096+d hold C_gate_d. Epilogue writes fp16 Bx = accEven*accOdd
//   and fp16 C_gate.
// ---------------------------------------------------------------------------
template <int MODE>
__global__ __launch_bounds__(128, 2)
void tf32_gemm(const float* __restrict__ A, const float* __restrict__ B,
               float* __restrict__ C, __half* __restrict__ CBx,
               __half* __restrict__ CCg, int N, int K) {
    extern __shared__ float sm[];
    const uint32_t smb = smem_u32(sm);

    const int tid    = threadIdx.x;
    const int wid    = tid >> 5;
    const int lane   = tid & 31;
    const int warp_m = wid >> 1;      // 0..1
    const int warp_n = wid & 1;       // 0..1
    const int lr     = lane >> 2;     // 0..7
    const int lc     = lane & 3;      // 0..3

    const int brow = blockIdx.y * BM;
    const int bcol = blockIdx.x * BN;

    const float* Ap = A + (size_t)brow * K;
    const float* Bp = B + 2 * (size_t)bcol;
    const size_t brs = 2 * (size_t)N;   // interleaved B row stride (floats)

    const int arow0 = tid >> 3;
    const int akc   = (tid & 7) * 4;
    const int brw   = tid >> 3;
    const int bcc   = (tid & 7) * 4;

    auto issue = [&](int kt, int buf) {
        uint32_t as = smb + (uint32_t)buf * STG_FLT * 4;
        uint32_t bs = as + A_SM * 4;
        #pragma unroll
        for (int i = 0; i < 8; i++) {
            int m = arow0 + i * 16;
            CP_ASYNC16(as + (uint32_t)(m * AST + akc) * 4,
                       Ap + (size_t)m * K + kt * BK + akc);
        }
        const float* bsrc = Bp + (size_t)(16 * kt + brw) * brs;
        #pragma unroll
        for (int i = 0; i < 8; i++) {
            int c = bcc + i * 32;
            CP_ASYNC16(bs + (uint32_t)(brw * BST + c) * 4, bsrc + c);
        }
    };

    float acc[4][8][4];
    #pragma unroll
    for (int mi = 0; mi < 4; mi++)
        #pragma unroll
        for (int ni = 0; ni < 8; ni++)
            #pragma unroll
            for (int q = 0; q < 4; q++)
                acc[mi][ni][q] = 0.0f;

    const int NK = K / BK;

    issue(0, 0); CP_COMMIT();
    issue(1, 1); CP_COMMIT();

    int buf = 0;
    for (int kt = 0; kt < NK; kt++) {
        CP_WAIT1();
        __syncthreads();

        if (kt + 2 < NK) {
            int nbuf = buf + 2; if (nbuf >= NSTAGE) nbuf -= NSTAGE;
            issue(kt + 2, nbuf);
        }
        CP_COMMIT();

        const float* As = sm + (size_t)buf * STG_FLT;
        const float* Bs = As + A_SM;

        #pragma unroll
        for (int ks = 0; ks < 4; ks++) {
            const int k0 = ks * 8;
            uint32_t a[4][4];
            #pragma unroll
            for (int mi = 0; mi < 4; mi++) {
                const int base = (warp_m * 64 + mi * 16 + lr) * AST + k0 + lc;
                a[mi][0] = __float_as_uint(As[base]);
                a[mi][1] = __float_as_uint(As[base + 8 * AST]);
                a[mi][2] = __float_as_uint(As[base + 4]);
                a[mi][3] = __float_as_uint(As[base + 8 * AST + 4]);
            }
            uint32_t b[8][2];
            #pragma unroll
            for (int ni = 0; ni < 8; ni++) {
                const int n = warp_n * 64 + ni * 8 + lr;
                float2 v = *(const float2*)(Bs + (ks * 4 + lc) * BST + 2 * n);
                b[ni][0] = __float_as_uint(v.x);
                b[ni][1] = __float_as_uint(v.y);
            }
            #pragma unroll
            for (int mi = 0; mi < 4; mi++)
                #pragma unroll
                for (int ni = 0; ni < 8; ni++)
                    mma_tf32(acc[mi][ni], a[mi], b[ni]);
        }

        if (++buf == NSTAGE) buf = 0;
    }

    // Epilogue
    if (MODE == 0) {
        #pragma unroll
        for (int mi = 0; mi < 4; mi++) {
            #pragma unroll
            for (int ni = 0; ni < 8; ni++) {
                const int r0 = brow + warp_m * 64 + mi * 16 + lr;
                const int c0 = bcol + warp_n * 64 + ni * 8 + lc * 2;
                *(float2*)(C + (size_t)r0 * N + c0)       = make_float2(acc[mi][ni][0], acc[mi][ni][1]);
                *(float2*)(C + (size_t)(r0 + 8) * N + c0) = make_float2(acc[mi][ni][2], acc[mi][ni][3]);
            }
        }
    } else if (bcol < 2 * DD) {
        // gated pairs: thread cols (c0, c0+1) = (B_gate_d, x_proj_d)
        #pragma unroll
        for (int mi = 0; mi < 4; mi++) {
            #pragma unroll
            for (int ni = 0; ni < 8; ni++) {
                const int r0 = brow + warp_m * 64 + mi * 16 + lr;
                const int d  = (bcol + warp_n * 64 + ni * 8 + lc * 2) >> 1;
                CBx[(size_t)r0 * DD + d]       = __float2half_rn(acc[mi][ni][0] * acc[mi][ni][1]);
                CBx[(size_t)(r0 + 8) * DD + d] = __float2half_rn(acc[mi][ni][2] * acc[mi][ni][3]);
            }
        }
    } else {
        #pragma unroll
        for (int mi = 0; mi < 4; mi++) {
            #pragma unroll
            for (int ni = 0; ni < 8; ni++) {
                const int r0 = brow + warp_m * 64 + mi * 16 + lr;
                const int c0 = bcol - 2 * DD + warp_n * 64 + ni * 8 + lc * 2;
                *(__half2*)(CCg + (size_t)r0 * DD + c0) =
                    __floats2half2_rn(acc[mi][ni][0], acc[mi][ni][1]);
                *(__half2*)(CCg + (size_t)(r0 + 8) * DD + c0) =
                    __floats2half2_rn(acc[mi][ni][2], acc[mi][ni][3]);
            }
        }
    }
}

// ---------------------------------------------------------------------------
// Elementwise tf32 rounding (float4 vectorized)
// ---------------------------------------------------------------------------
__global__ void cvt_tf32_kernel(const float* __restrict__ in, float* __restrict__ out,
                                size_t n4) {
    size_t i = (size_t)blockIdx.x * blockDim.x + threadIdx.x;
    if (i >= n4) return;
    float4 v = ((const float4*)in)[i];
    v.x = f2tf32(v.x); v.y = f2tf32(v.y); v.z = f2tf32(v.z); v.w = f2tf32(v.w);
    ((float4*)out)[i] = v;
}

// ---------------------------------------------------------------------------
// W [K][N] -> pair-interleaved [K/2][2N'], optional source-column remap:
//   remap(n) = n<4096 ? (n odd ? 2D+n/2 : n/2) : D + (n-4096)
// out[kb*4+p][2n+h] = tf32(W[kb*8+p+4h][remap(n)]).
// ---------------------------------------------------------------------------
template <int REMAP>
__global__ void wtrans_kernel(const float* __restrict__ in, float* __restrict__ out,
                              int N) {
    __shared__ float s[8][257];
    const int kb = blockIdx.y;
    const int n0 = blockIdx.x * 256;
    const int tid = threadIdx.x;

    int n = n0 + tid;
    int src;
    if (REMAP) {
        src = (n < 2 * DD) ? ((n & 1) ? 2 * DD + (n >> 1) : (n >> 1))
                           : DD + (n - 2 * DD);
    } else {
        src = n;
    }
    #pragma unroll
    for (int j = 0; j < 8; j++)
        s[j][tid] = f2tf32(in[(size_t)(kb * 8 + j) * N + src]);
    __syncthreads();

    const int p  = tid >> 6;
    const int j0 = tid & 63;
    #pragma unroll
    for (int h = 0; h < 2; h++) {
        int j = j0 + h * 64;
        float4 v = make_float4(s[p][2 * j], s[p + 4][2 * j],
                               s[p][2 * j + 1], s[p + 4][2 * j + 1]);
        *(float4*)(out + (size_t)(kb * 4 + p) * (2 * N) + 2 * n0 + 4 * j) = v;
    }
}

// ---------------------------------------------------------------------------
// s-chunked conv + gate from fp16 Bx / C_gate.
// Grid (DD/512, SS/32, BB), 256 threads; each thread owns a d-pair and
// walks 32 consecutive s with Bx[s-1], Bx[s-2] rolling in registers.
// y = tf32( Cg[s] * (w2*Bx[s] + w1*Bx[s-1] + w0*Bx[s-2]) )
// ---------------------------------------------------------------------------
#define SCH 32
__global__ __launch_bounds__(256)
void conv_gate_kernel(const float* __restrict__ conv_w,
                      float* __restrict__ y) {
    const int dp = blockIdx.x * 256 + threadIdx.x;   // d-pair index (d = 2*dp)
    const int s0 = blockIdx.y * SCH;
    const size_t mbase = (size_t)blockIdx.z * SS;

    const int d = 2 * dp;
    const float w0a = conv_w[d * LL + 0];
    const float w1a = conv_w[d * LL + 1];
    const float w2a = conv_w[d * LL + 2];
    const float w0b = conv_w[(d + 1) * LL + 0];
    const float w1b = conv_w[(d + 1) * LL + 1];
    const float w2b = conv_w[(d + 1) * LL + 2];

    const __half2* BxH = (const __half2*)g_BxH;
    const __half2* CgH = (const __half2*)g_CgH;
    const int HP = DD / 2;   // half2 row stride

    float2 bx1 = (s0 >= 1) ? __half22float2(BxH[(mbase + s0 - 1) * HP + dp])
                           : make_float2(0.f, 0.f);
    float2 bx2 = (s0 >= 2) ? __half22float2(BxH[(mbase + s0 - 2) * HP + dp])
                           : make_float2(0.f, 0.f);

    #pragma unroll 4
    for (int i = 0; i < SCH; i++) {
        const size_t m = mbase + s0 + i;
        float2 bx0 = __half22float2(BxH[m * HP + dp]);
        float2 cg  = __half22float2(CgH[m * HP + dp]);

        float ca = w2a * bx0.x + w1a * bx1.x + w0a * bx2.x;
        float cb = w2b * bx0.y + w1b * bx1.y + w0b * bx2.y;
        *(float2*)(y + m * DD + d) =
            make_float2(f2tf32(cg.x * ca), f2tf32(cg.y * cb));

        bx2 = bx1;
        bx1 = bx0;
    }
}

// ---------------------------------------------------------------------------
extern "C" void kernel_launch(void* const* d_in, const int* in_sizes, int n_in,
                              void* d_out, int out_size) {
    const float* x      = (const float*)d_in[0];
    const float* W_in   = (const float*)d_in[1];
    const float* conv_w = (const float*)d_in[2];
    const float* W_out  = (const float*)d_in[3];
    float*       out    = (float*)d_out;

    float *y, *xc, *Win, *Wout;
    __half *BxH, *CgH;
    cudaGetSymbolAddress((void**)&BxH,  g_BxH);
    cudaGetSymbolAddress((void**)&CgH,  g_CgH);
    cudaGetSymbolAddress((void**)&y,    g_y);
    cudaGetSymbolAddress((void**)&xc,   g_xc);
    cudaGetSymbolAddress((void**)&Win,  g_Win);
    cudaGetSymbolAddress((void**)&Wout, g_Wout);

    cudaFuncSetAttribute((const void*)tf32_gemm<1>,
                         cudaFuncAttributeMaxDynamicSharedMemorySize, SMEM_BYTES);
    cudaFuncSetAttribute((const void*)tf32_gemm<0>,
                         cudaFuncAttributeMaxDynamicSharedMemorySize, SMEM_BYTES);

    // Pre-passes: tf32 rounding (x) + weight transforms
    {
        size_t n4 = (size_t)MTOT * DD / 4;
        cvt_tf32_kernel<<<(unsigned)((n4 + 255) / 256), 256>>>(x, xc, n4);
        wtrans_kernel<1><<<dim3(TRIPLE / 256, DD / 8), 256>>>(W_in, Win, TRIPLE);
        wtrans_kernel<0><<<dim3(DD / 256, DD / 8), 256>>>(W_out, Wout, DD);
    }

    // GEMM1 (gated): writes fp16 Bx = B_gate*x_proj and fp16 C_gate
    tf32_gemm<1><<<dim3(TRIPLE / BN, MTOT / BM), 128, SMEM_BYTES>>>(
        xc, Win, nullptr, BxH, CgH, TRIPLE, DD);

    // Conv + gate -> y (tf32-rounded), s-chunked
    conv_gate_kernel<<<dim3(DD / 512, SS / SCH, BB), 256>>>(conv_w, y);

    // GEMM2: out = y @ W_out
    tf32_gemm<0><<<dim3(DD / BN, MTOT / BM), 128, SMEM_BYTES>>>(
        y, Wout, out, nullptr, nullptr, DD, DD);
}

// round 17
// speedup vs baseline: 2.7585x; 1.8791x over previous
#include <cuda_runtime.h>
#include <cuda_fp16.h>
#include <cstdint>

// Problem constants
#define BB 4
#define SS 4096
#define DD 2048
#define LL 3
#define TRIPLE (3 * DD)
#define MTOT (BB * SS)          // 16384

// FP16 GEMM tiling: CTA 128x128, 4 warps (2x2), warp tile 64x64,
// BK=32 halves, 3-stage cp.async, 2 CTAs/SM, single barrier per k-tile.
// A smem: [128][40] halves, natural k order.
// B smem: [8][264] u32 rows; row (ks*4+lc), u32 col 2n/2n+1 hold half2
//   (k,k+1) for k = 16ks+2lc and k = 16ks+2lc+8  -> one LDS.64 per B frag.
#define BM 128
#define BN 128
#define BKH 32                  // k halves per tile
#define NSTAGE 3
#define ASTH 40                 // A smem row stride (halves): 32 + 8 pad
#define A_SMH (BM * ASTH)       // 5120 halves = 10240 B
#define BST32 264               // B smem row stride (u32): 256 + 8 pad
#define B_SM32 (8 * BST32)      // 2112 u32 = 8448 B
#define STG_BYTES (A_SMH * 2 + B_SM32 * 4)   // 18688 B
#define SMEM_BYTES (NSTAGE * STG_BYTES)      // 56064 B

// Scratch (__device__ globals: allocation-free rule)
__device__ __half   g_BxH[(size_t)MTOT * DD];    // B_gate*x_proj (fp16)
__device__ __half   g_CgH[(size_t)MTOT * DD];    // C_gate (fp16)
__device__ __half   g_yh[(size_t)MTOT * DD];     // GEMM2 A (fp16, natural [M][K])
__device__ __half   g_xh[(size_t)MTOT * DD];     // x (fp16, natural [M][K])
__device__ uint32_t g_Win[(size_t)(DD / 4) * (2 * TRIPLE)];  // W_in  packed fp16
__device__ uint32_t g_Wout[(size_t)(DD / 4) * (2 * DD)];     // W_out packed fp16

__device__ __forceinline__ uint32_t smem_u32(const void* p) {
    uint32_t a;
    asm("{ .reg .u64 t; cvta.to.shared.u64 t, %1; cvt.u32.u64 %0, t; }" : "=r"(a) : "l"(p));
    return a;
}

#define CP_ASYNC16(dst, src) \
    asm volatile("cp.async.cg.shared.global [%0], [%1], 16;" :: "r"(dst), "l"(src))
#define CP_COMMIT() asm volatile("cp.async.commit_group;" ::: "memory")
#define CP_WAIT1()  asm volatile("cp.async.wait_group 1;" ::: "memory")

__device__ __forceinline__ void mma_f16(float c[4], const uint32_t a[4], const uint32_t b[2]) {
    asm volatile(
        "mma.sync.aligned.m16n8k16.row.col.f32.f16.f16.f32 "
        "{%0,%1,%2,%3}, {%4,%5,%6,%7}, {%8,%9}, {%0,%1,%2,%3};"
        : "+f"(c[0]), "+f"(c[1]), "+f"(c[2]), "+f"(c[3])
        : "r"(a[0]), "r"(a[1]), "r"(a[2]), "r"(a[3]), "r"(b[0]), "r"(b[1]));
}

// ---------------------------------------------------------------------------
// FP16 mma.sync GEMM: C = A @ B. A fp16 row-major [M][K] halves.
// B packed u32 [K/4][2N]: row (4*k16 + p), col 2n+h = half2(W[16k16+2p+8h][n],
// W[16k16+2p+8h+1][n]).  MODE 0: plain fp32 C write.
// MODE 1 (GEMM1 gated): cols 2d/2d+1 (n<4096) = (B_gate_d, x_proj_d),
//   cols 4096+d = C_gate_d. Writes fp16 Bx = accEven*accOdd and fp16 C_gate.
// ---------------------------------------------------------------------------
template <int MODE>
__global__ __launch_bounds__(128, 2)
void f16_gemm(const __half* __restrict__ A, const uint32_t* __restrict__ B,
              float* __restrict__ C, __half* __restrict__ CBx,
              __half* __restrict__ CCg, int N, int K) {
    extern __shared__ char smraw[];
    const uint32_t smb = smem_u32(smraw);

    const int tid    = threadIdx.x;
    const int wid    = tid >> 5;
    const int lane   = tid & 31;
    const int warp_m = wid >> 1;      // 0..1
    const int warp_n = wid & 1;       // 0..1
    const int lr     = lane >> 2;     // 0..7
    const int lc     = lane & 3;      // 0..3

    const int brow = blockIdx.y * BM;
    const int bcol = blockIdx.x * BN;

    const __half* Ap = A + (size_t)brow * K;
    const uint32_t* Bp = B + 2 * (size_t)bcol;
    const size_t brs = 2 * (size_t)N;   // packed B row stride (u32)

    // cp.async coords (128 threads)
    // A tile: 128 rows x 64B = 512 chunks -> 4/thread
    const int arow0 = tid >> 2;             // +i*32
    const int akh   = (tid & 3) * 8;        // half offset within row
    // B tile: 8 rows x 1024B = 512 chunks -> 4/thread
    const int brw   = tid >> 4;             // 0..7
    const int bcc   = (tid & 15) * 4;       // +i*64 (u32 cols)

    auto issue = [&](int kt, int buf) {
        uint32_t as = smb + (uint32_t)buf * STG_BYTES;
        uint32_t bs = as + A_SMH * 2;
        #pragma unroll
        for (int i = 0; i < 4; i++) {
            int m = arow0 + i * 32;
            CP_ASYNC16(as + (uint32_t)(m * ASTH + akh) * 2,
                       Ap + (size_t)m * K + kt * BKH + akh);
        }
        const uint32_t* bsrc = Bp + (size_t)(8 * kt + brw) * brs;
        #pragma unroll
        for (int i = 0; i < 4; i++) {
            int c = bcc + i * 64;
            CP_ASYNC16(bs + (uint32_t)(brw * BST32 + c) * 4, bsrc + c);
        }
    };

    float acc[4][8][4];
    #pragma unroll
    for (int mi = 0; mi < 4; mi++)
        #pragma unroll
        for (int ni = 0; ni < 8; ni++)
            #pragma unroll
            for (int q = 0; q < 4; q++)
                acc[mi][ni][q] = 0.0f;

    const int NK = K / BKH;

    issue(0, 0); CP_COMMIT();
    issue(1, 1); CP_COMMIT();

    int buf = 0;
    for (int kt = 0; kt < NK; kt++) {
        CP_WAIT1();
        __syncthreads();

        if (kt + 2 < NK) {
            int nbuf = buf + 2; if (nbuf >= NSTAGE) nbuf -= NSTAGE;
            issue(kt + 2, nbuf);
        }
        CP_COMMIT();

        const __half* As = (const __half*)(smraw + (size_t)buf * STG_BYTES);
        const uint32_t* Bs = (const uint32_t*)(smraw + (size_t)buf * STG_BYTES + A_SMH * 2);

        #pragma unroll
        for (int ks = 0; ks < 2; ks++) {        // two K=16 steps cover BKH=32
            const int k0 = ks * 16;
            uint32_t a[4][4];
            #pragma unroll
            for (int mi = 0; mi < 4; mi++) {
                const __half* p0 = As + (warp_m * 64 + mi * 16 + lr) * ASTH + k0 + 2 * lc;
                const __half* p1 = p0 + 8 * ASTH;
                a[mi][0] = *(const uint32_t*)p0;
                a[mi][1] = *(const uint32_t*)p1;
                a[mi][2] = *(const uint32_t*)(p0 + 8);
                a[mi][3] = *(const uint32_t*)(p1 + 8);
            }
            uint32_t b[8][2];
            #pragma unroll
            for (int ni = 0; ni < 8; ni++) {
                const int n = warp_n * 64 + ni * 8 + lr;
                uint2 v = *(const uint2*)(Bs + (ks * 4 + lc) * BST32 + 2 * n);
                b[ni][0] = v.x;
                b[ni][1] = v.y;
            }
            #pragma unroll
            for (int mi = 0; mi < 4; mi++)
                #pragma unroll
                for (int ni = 0; ni < 8; ni++)
                    mma_f16(acc[mi][ni], a[mi], b[ni]);
        }

        if (++buf == NSTAGE) buf = 0;
    }

    // Epilogue
    if (MODE == 0) {
        #pragma unroll
        for (int mi = 0; mi < 4; mi++) {
            #pragma unroll
            for (int ni = 0; ni < 8; ni++) {
                const int r0 = brow + warp_m * 64 + mi * 16 + lr;
                const int c0 = bcol + warp_n * 64 + ni * 8 + lc * 2;
                *(float2*)(C + (size_t)r0 * N + c0)       = make_float2(acc[mi][ni][0], acc[mi][ni][1]);
                *(float2*)(C + (size_t)(r0 + 8) * N + c0) = make_float2(acc[mi][ni][2], acc[mi][ni][3]);
            }
        }
    } else if (bcol < 2 * DD) {
        // gated pairs: thread cols (c0, c0+1) = (B_gate_d, x_proj_d)
        #pragma unroll
        for (int mi = 0; mi < 4; mi++) {
            #pragma unroll
            for (int ni = 0; ni < 8; ni++) {
                const int r0 = brow + warp_m * 64 + mi * 16 + lr;
                const int d  = (bcol + warp_n * 64 + ni * 8 + lc * 2) >> 1;
                CBx[(size_t)r0 * DD + d]       = __float2half_rn(acc[mi][ni][0] * acc[mi][ni][1]);
                CBx[(size_t)(r0 + 8) * DD + d] = __float2half_rn(acc[mi][ni][2] * acc[mi][ni][3]);
            }
        }
    } else {
        #pragma unroll
        for (int mi = 0; mi < 4; mi++) {
            #pragma unroll
            for (int ni = 0; ni < 8; ni++) {
                const int r0 = brow + warp_m * 64 + mi * 16 + lr;
                const int c0 = bcol - 2 * DD + warp_n * 64 + ni * 8 + lc * 2;
                *(__half2*)(CCg + (size_t)r0 * DD + c0) =
                    __floats2half2_rn(acc[mi][ni][0], acc[mi][ni][1]);
                *(__half2*)(CCg + (size_t)(r0 + 8) * DD + c0) =
                    __floats2half2_rn(acc[mi][ni][2], acc[mi][ni][3]);
            }
        }
    }
}

// ---------------------------------------------------------------------------
// x -> fp16 copy (float4 -> 2x half2)
// ---------------------------------------------------------------------------
__global__ void cvt_f16_kernel(const float* __restrict__ in, __half* __restrict__ out,
                               size_t n4) {
    size_t i = (size_t)blockIdx.x * blockDim.x + threadIdx.x;
    if (i >= n4) return;
    float4 v = ((const float4*)in)[i];
    __half2 h0 = __floats2half2_rn(v.x, v.y);
    __half2 h1 = __floats2half2_rn(v.z, v.w);
    ((__half2*)out)[2 * i]     = h0;
    ((__half2*)out)[2 * i + 1] = h1;
}

// ---------------------------------------------------------------------------
// W [K][N] fp32 -> packed fp16 u32 [K/4][2N'], optional source-column remap:
//   remap(n) = n<4096 ? (n odd ? 2D+n/2 : n/2) : D + (n-4096)
// out[(4*k16 + p)][2n+h] = half2(W[16k16+2p+8h][n'], W[16k16+2p+8h+1][n'])
// Block: one k16 (16 rows) x 128 n-cols; 256 threads.
// ---------------------------------------------------------------------------
template <int REMAP>
__global__ void wtrans_kernel(const float* __restrict__ in, uint32_t* __restrict__ out,
                              int N) {
    __shared__ float s[16][129];
    const int k16 = blockIdx.y;
    const int n0  = blockIdx.x * 128;
    const int tid = threadIdx.x;

    // Load 16x128 tile (remapped source cols)
    #pragma unroll
    for (int i = 0; i < 8; i++) {
        int e = tid + i * 256;          // 0..2047
        int row = e >> 7, col = e & 127;
        int n = n0 + col;
        int src;
        if (REMAP) {
            src = (n < 2 * DD) ? ((n & 1) ? 2 * DD + (n >> 1) : (n >> 1))
                               : DD + (n - 2 * DD);
        } else {
            src = n;
        }
        s[row][col] = in[(size_t)(k16 * 16 + row) * N + src];
    }
    __syncthreads();

    // Write 4 p-rows x 256 u32 cols = 1024 u32; 4 per thread
    const int p = tid >> 6;             // 0..3
    #pragma unroll
    for (int j = 0; j < 4; j++) {
        int oc = (tid & 63) * 4 + j;    // 0..255
        int n  = oc >> 1;
        int h  = oc & 1;
        int kl = 2 * p + 8 * h;
        __half2 v = __floats2half2_rn(s[kl][n], s[kl + 1][n]);
        out[(size_t)(k16 * 4 + p) * (2 * N) + 2 * n0 + oc] = *(uint32_t*)&v;
    }
}

// ---------------------------------------------------------------------------
// s-chunked conv + gate from fp16 Bx / C_gate -> fp16 y.
// Grid (DD/512, SS/32, BB), 256 threads; thread owns a d-pair, walks 32 s.
// ---------------------------------------------------------------------------
#define SCH 32
__global__ __launch_bounds__(256)
void conv_gate_kernel(const float* __restrict__ conv_w,
                      __half* __restrict__ y) {
    const int dp = blockIdx.x * 256 + threadIdx.x;   // d-pair index (d = 2*dp)
    const int s0 = blockIdx.y * SCH;
    const size_t mbase = (size_t)blockIdx.z * SS;

    const int d = 2 * dp;
    const float w0a = conv_w[d * LL + 0];
    const float w1a = conv_w[d * LL + 1];
    const float w2a = conv_w[d * LL + 2];
    const float w0b = conv_w[(d + 1) * LL + 0];
    const float w1b = conv_w[(d + 1) * LL + 1];
    const float w2b = conv_w[(d + 1) * LL + 2];

    const __half2* BxH = (const __half2*)g_BxH;
    const __half2* CgH = (const __half2*)g_CgH;
    __half2* yH = (__half2*)y;
    const int HP = DD / 2;

    float2 bx1 = (s0 >= 1) ? __half22float2(BxH[(mbase + s0 - 1) * HP + dp])
                           : make_float2(0.f, 0.f);
    float2 bx2 = (s0 >= 2) ? __half22float2(BxH[(mbase + s0 - 2) * HP + dp])
                           : make_float2(0.f, 0.f);

    #pragma unroll 4
    for (int i = 0; i < SCH; i++) {
        const size_t m = mbase + s0 + i;
        float2 bx0 = __half22float2(BxH[m * HP + dp]);
        float2 cg  = __half22float2(CgH[m * HP + dp]);

        float ca = w2a * bx0.x + w1a * bx1.x + w0a * bx2.x;
        float cb = w2b * bx0.y + w1b * bx1.y + w0b * bx2.y;
        yH[m * HP + dp] = __floats2half2_rn(cg.x * ca, cg.y * cb);

        bx2 = bx1;
        bx1 = bx0;
    }
}

// ---------------------------------------------------------------------------
extern "C" void kernel_launch(void* const* d_in, const int* in_sizes, int n_in,
                              void* d_out, int out_size) {
    const float* x      = (const float*)d_in[0];
    const float* W_in   = (const float*)d_in[1];
    const float* conv_w = (const float*)d_in[2];
    const float* W_out  = (const float*)d_in[3];
    float*       out    = (float*)d_out;

    __half *BxH, *CgH, *yh, *xh;
    uint32_t *Win, *Wout;
    cudaGetSymbolAddress((void**)&BxH,  g_BxH);
    cudaGetSymbolAddress((void**)&CgH,  g_CgH);
    cudaGetSymbolAddress((void**)&yh,   g_yh);
    cudaGetSymbolAddress((void**)&xh,   g_xh);
    cudaGetSymbolAddress((void**)&Win,  g_Win);
    cudaGetSymbolAddress((void**)&Wout, g_Wout);

    cudaFuncSetAttribute((const void*)f16_gemm<1>,
                         cudaFuncAttributeMaxDynamicSharedMemorySize, SMEM_BYTES);
    cudaFuncSetAttribute((const void*)f16_gemm<0>,
                         cudaFuncAttributeMaxDynamicSharedMemorySize, SMEM_BYTES);

    // Pre-passes: fp16 conversion (x) + weight pack transforms
    {
        size_t n4 = (size_t)MTOT * DD / 4;
        cvt_f16_kernel<<<(unsigned)((n4 + 255) / 256), 256>>>(x, xh, n4);
        wtrans_kernel<1><<<dim3(TRIPLE / 128, DD / 16), 256>>>(W_in, Win, TRIPLE);
        wtrans_kernel<0><<<dim3(DD / 128, DD / 16), 256>>>(W_out, Wout, DD);
    }

    // GEMM1 (gated): writes fp16 Bx = B_gate*x_proj and fp16 C_gate
    f16_gemm<1><<<dim3(TRIPLE / BN, MTOT / BM), 128, SMEM_BYTES>>>(
        xh, Win, nullptr, BxH, CgH, TRIPLE, DD);

    // Conv + gate -> y (fp16), s-chunked
    conv_gate_kernel<<<dim3(DD / 512, SS / SCH, BB), 256>>>(conv_w, yh);

    // GEMM2: out = y @ W_out
    f16_gemm<0><<<dim3(DD / BN, MTOT / BM), 128, SMEM_BYTES>>>(
        yh, Wout, out, nullptr, nullptr, DD, DD);
}